// round 12
// baseline (speedup 1.0000x reference)
#include <cuda_runtime.h>
#include <cstdint>

#define Bsz 2048
#define Tsz 512
#define Asz 32
#define Hsz 16
#define NCHUNK (Tsz / 8)

typedef unsigned long long u64;
typedef unsigned int u32;

__device__ __forceinline__ u64 pack2(float lo, float hi) {
    u64 r; asm("mov.b64 %0, {%1, %2};" : "=l"(r) : "f"(lo), "f"(hi)); return r;
}
__device__ __forceinline__ void unpack2(u64 v, float& lo, float& hi) {
    asm("mov.b64 {%0, %1}, %2;" : "=f"(lo), "=f"(hi) : "l"(v));
}
__device__ __forceinline__ u64 fma2(u64 a, u64 b, u64 c) {
    u64 d; asm("fma.rn.f32x2 %0, %1, %2, %3;" : "=l"(d) : "l"(a), "l"(b), "l"(c)); return d;
}
__device__ __forceinline__ u64 add2(u64 a, u64 b) {
    u64 d; asm("add.rn.f32x2 %0, %1, %2;" : "=l"(d) : "l"(a), "l"(b)); return d;
}
__device__ __forceinline__ float hsum2(u64 v) {
    float lo, hi; unpack2(v, lo, hi); return lo + hi;
}
__device__ __forceinline__ float tanh_fast(float x) {
    float y; asm("tanh.approx.f32 %0, %1;" : "=f"(y) : "f"(x)); return y;
}
__device__ __forceinline__ float sigmoid_fast(float x) {
    return fmaf(0.5f, tanh_fast(0.5f * x), 0.5f);
}
__device__ __forceinline__ u32 smaddr(const void* p) {
    return (u32)__cvta_generic_to_shared(p);
}
__device__ __forceinline__ void cp16(u32 s, const void* g) {
    asm volatile("cp.async.ca.shared.global [%0], [%1], 16;" :: "r"(s), "l"(g));
}
#define CP_COMMIT() asm volatile("cp.async.commit_group;" ::: "memory")
#define CP_WAIT1()  asm volatile("cp.async.wait_group 1;" ::: "memory")

// ============================================================================
// CTA = 128 threads = 4 warps = 4 batch elements; grid 512 = ONE wave.
//   consumer warp (2 elems, half-warp each): recurrence with all-4-gates
//     in-lane (no shfl on the c chain), h stored DUPLICATED (h,h) so packed
//     (i,g)/(f,o) weight pairs make gate sums land pre-paired with pg layout
//     (zero hsum/unpack for gates). Actor heads one chunk BEHIND from the
//     h-ring, packed weights reloaded from smem per chunk (transient regs).
//   producer warp (2 elems): x pregates one chunk AHEAD (cp.async double
//     buffer) + critic one chunk BEHIND (16-lane trick on the h-ring).
// Roles flip with blockIdx parity. One __syncthreads per chunk.
// ============================================================================
__global__ void __launch_bounds__(128, 4) lstm_fused(
    const float* __restrict__ xin, const float* __restrict__ masks,
    const float* __restrict__ h0, const float* __restrict__ c0,
    const float* __restrict__ w_ih, const float* __restrict__ w_hh,
    const float* __restrict__ b_ih, const float* __restrict__ b_hh,
    const float* __restrict__ w_actor, const float* __restrict__ b_actor,
    const float* __restrict__ w_critic, const float* __restrict__ b_critic,
    float* __restrict__ actor, float* __restrict__ critic,
    float* __restrict__ hT, float* __restrict__ cT)
{
    __shared__ __align__(16) float pgsm[4][2][8 * 64];   // 16KB
    __shared__ __align__(16) float xsm[4][2][8 * 32];    // 8KB
    __shared__ __align__(16) float hb2[4][16][32];       // 8KB ring, (h,h) pairs
    __shared__ __align__(16) u64 wact2_s[16][18];        // packed actor rows (2j,2j+1)
    __shared__ __align__(16) u64 wcd_s[16];              // (wc_k, wc_k)
    __shared__ __align__(16) float2 bact2_s[16];

    const int tid  = threadIdx.x;
    const int w    = tid >> 5;
    const int lane = tid & 31;
    const int sub  = w & 1;
    const bool is_prod = (((w >> 1) ^ blockIdx.x) & 1) != 0;
    const int e0   = 2 * sub;
    const int b0   = blockIdx.x * 4;

    // packed head-weight tables
    for (int i = tid; i < 256; i += 128) {
        const int j = i >> 4, k = i & 15;
        wact2_s[j][k] = pack2(w_actor[(2 * j) * 16 + k], w_actor[(2 * j + 1) * 16 + k]);
    }
    if (tid < 16) {
        wcd_s[tid] = pack2(w_critic[tid], w_critic[tid]);
        bact2_s[tid] = make_float2(b_actor[2 * tid], b_actor[2 * tid + 1]);
    }

    if (is_prod) {
        // ---------------- PRODUCER (elems e0, e0+1) ----------------
        u64 wA[16], wB[16];
        {
            const u64* pA = (const u64*)(w_ih + lane * 32);
            const u64* pB = (const u64*)(w_ih + (32 + lane) * 32);
#pragma unroll
            for (int k = 0; k < 16; k++) { wA[k] = pA[k]; wB[k] = pB[k]; }
        }
        const float bsA = b_ih[lane] + b_hh[lane];
        const float bsB = b_ih[32 + lane] + b_hh[32 + lane];
        const float bcr = b_critic[0];

        const float* xbA = xin + (size_t)(b0 + e0) * Tsz * Asz;
        const float* xbB = xin + (size_t)(b0 + e0 + 1) * Tsz * Asz;
        float* crA = critic + (size_t)(b0 + e0) * Tsz;
        float* crB = critic + (size_t)(b0 + e0 + 1) * Tsz;

        auto loadx = [&](int ch) {
            const int bf = ch & 1;
            u32 dA = smaddr(&xsm[e0][bf][0]);
            u32 dB = smaddr(&xsm[e0 + 1][bf][0]);
            const float* sA = xbA + ch * 256;
            const float* sB = xbB + ch * 256;
            cp16(dA + lane * 16,       sA + lane * 4);
            cp16(dA + lane * 16 + 512, sA + lane * 4 + 128);
            cp16(dB + lane * 16,       sB + lane * 4);
            cp16(dB + lane * 16 + 512, sB + lane * 4 + 128);
        };
        auto comp = [&](int ch) {
            const int bf = ch & 1;
#pragma unroll
            for (int ee = 0; ee < 2; ee++) {
#pragma unroll
                for (int s = 0; s < 8; s++) {
                    const ulonglong2* xp = (const ulonglong2*)&xsm[e0 + ee][bf][s * 32];
                    u64 a0 = 0, a1 = 0, g0 = 0, g1 = 0;
#pragma unroll
                    for (int q = 0; q < 8; q++) {
                        const ulonglong2 v = xp[q];
                        a0 = fma2(wA[2 * q],     v.x, a0);
                        a1 = fma2(wA[2 * q + 1], v.y, a1);
                        g0 = fma2(wB[2 * q],     v.x, g0);
                        g1 = fma2(wB[2 * q + 1], v.y, g1);
                    }
                    float2 o;
                    o.x = hsum2(add2(a0, a1)) + bsA;
                    o.y = hsum2(add2(g0, g1)) + bsB;
                    *(float2*)&pgsm[e0 + ee][bf][s * 64 + 2 * lane] = o;
                }
            }
        };
        auto do_critic = [&](int cc) {              // chunk cc: h final in ring
            if (lane < 16) {
                const int ee = lane >> 3, s = lane & 7;
                const int t = cc * 8 + s;
                const u64* hp = (const u64*)&hb2[e0 + ee][t & 15][0];
                u64 a0 = 0, a1 = 0;
#pragma unroll
                for (int k = 0; k < 8; k++) {
                    a0 = fma2(wcd_s[2 * k],     hp[2 * k],     a0);
                    a1 = fma2(wcd_s[2 * k + 1], hp[2 * k + 1], a1);
                }
                float lo, hi;
                unpack2(add2(a0, a1), lo, hi);
                (ee ? crB : crA)[t] = lo + bcr;     // both halves equal; take lo
            }
        };

        loadx(0); CP_COMMIT();
        loadx(1); CP_COMMIT();
        CP_WAIT1();
        comp(0);
        __syncthreads();                            // pg chunk 0 ready

        for (int cc = 0; cc < NCHUNK; cc++) {
            if (cc + 2 < NCHUNK) loadx(cc + 2);
            CP_COMMIT();
            CP_WAIT1();                             // x_{cc+1} landed
            if (cc + 1 < NCHUNK) comp(cc + 1);
            if (cc >= 1) do_critic(cc - 1);
            __syncthreads();
        }
        do_critic(NCHUNK - 1);
    } else {
        // ---------------- CONSUMER (half-warp per elem) ----------------
        const int el = lane >> 4;
        const int e  = e0 + el;
        const int j  = lane & 15;
        const int b  = b0 + e;

        // packed gate weights: whIG[k] = (w_i[j][k], w_g[j][k]); whFO likewise
        u64 whIG[16], whFO[16];
#pragma unroll
        for (int k = 0; k < 16; k++) {
            whIG[k] = pack2(w_hh[j * 16 + k],        w_hh[(32 + j) * 16 + k]);
            whFO[k] = pack2(w_hh[(16 + j) * 16 + k], w_hh[(48 + j) * 16 + k]);
        }
        const float* mb = masks + (size_t)b * Tsz;
        float* actb     = actor + (size_t)b * Tsz * Asz;

        float c = c0[b * Hsz + j];
        {
            const float hv0 = h0[b * Hsz + j];
            *(float2*)&hb2[e][15][2 * j] = make_float2(hv0, hv0);   // h_{-1}
        }
        float m_cur = mb[0];
        float h2 = 0.0f;

        __syncthreads();                            // match producer prologue

        for (int cc = 0; cc < NCHUNK; cc++) {
            // ---- actor heads for chunk cc-1 (smem reload after barrier
            //      prevents hoisting -> weights stay transient)
            if (cc >= 1) {
                u64 wab[16];
#pragma unroll
                for (int k = 0; k < 16; k++) wab[k] = wact2_s[j][k];
                const float2 bv = bact2_s[j];
                const int t0 = (cc - 1) * 8;
#pragma unroll
                for (int s = 0; s < 8; s++) {
                    const int t = t0 + s;
                    const ulonglong2* hp = (const ulonglong2*)&hb2[e][t & 15][0];
                    u64 A0 = 0, A1 = 0;
#pragma unroll
                    for (int q = 0; q < 8; q++) {
                        const ulonglong2 v = hp[q];
                        A0 = fma2(wab[2 * q],     v.x, A0);
                        A1 = fma2(wab[2 * q + 1], v.y, A1);
                    }
                    float sa, sb;
                    unpack2(add2(A0, A1), sa, sb);
                    *(float2*)&actb[t * Asz + 2 * j] = make_float2(sa + bv.x, sb + bv.y);
                }
            }
            // ---- recurrence steps
#pragma unroll
            for (int s = 0; s < 8; s++) {
                const int t = cc * 8 + s;
                const float m = m_cur;
                m_cur = mb[(t + 1 < Tsz) ? t + 1 : Tsz - 1];
                const u64 m2 = pack2(m, m);
                const float cm = c * m;

                const ulonglong2* hp = (const ulonglong2*)&hb2[e][(t + 15) & 15][0];
                u64 aIG0 = 0, aIG1 = 0, aFO0 = 0, aFO1 = 0;
#pragma unroll
                for (int q = 0; q < 8; q++) {
                    const ulonglong2 v = hp[q];        // ((h2q,h2q),(h2q+1,h2q+1))
                    aIG0 = fma2(whIG[2 * q],     v.x, aIG0);
                    aIG1 = fma2(whIG[2 * q + 1], v.y, aIG1);
                    aFO0 = fma2(whFO[2 * q],     v.x, aFO0);
                    aFO1 = fma2(whFO[2 * q + 1], v.y, aFO1);
                }
                const u64 pIG = *(const u64*)&pgsm[e][cc & 1][s * 64 + 2 * j];
                const u64 pFO = *(const u64*)&pgsm[e][cc & 1][s * 64 + 32 + 2 * j];
                const u64 gIG = fma2(m2, add2(aIG0, aIG1), pIG);
                const u64 gFO = fma2(m2, add2(aFO0, aFO1), pFO);
                float gI, gG, gF, gO;
                unpack2(gIG, gI, gG);
                unpack2(gFO, gF, gO);

                const float vI = sigmoid_fast(gI);
                const float vF = sigmoid_fast(gF);
                const float vO = sigmoid_fast(gO);
                const float vG = tanh_fast(gG);

                c  = fmaf(vF, cm, vI * vG);
                h2 = vO * tanh_fast(c);

                *(float2*)&hb2[e][t & 15][2 * j] = make_float2(h2, h2);
                __syncwarp();
            }
            __syncthreads();
        }

        // ---- tail: actor heads for the last chunk
        {
            u64 wab[16];
#pragma unroll
            for (int k = 0; k < 16; k++) wab[k] = wact2_s[j][k];
            const float2 bv = bact2_s[j];
            const int t0 = (NCHUNK - 1) * 8;
#pragma unroll
            for (int s = 0; s < 8; s++) {
                const int t = t0 + s;
                const ulonglong2* hp = (const ulonglong2*)&hb2[e][t & 15][0];
                u64 A0 = 0, A1 = 0;
#pragma unroll
                for (int q = 0; q < 8; q++) {
                    const ulonglong2 v = hp[q];
                    A0 = fma2(wab[2 * q],     v.x, A0);
                    A1 = fma2(wab[2 * q + 1], v.y, A1);
                }
                float sa, sb;
                unpack2(add2(A0, A1), sa, sb);
                *(float2*)&actb[t * Asz + 2 * j] = make_float2(sa + bv.x, sb + bv.y);
            }
        }

        hT[b * Hsz + j] = h2;
        cT[b * Hsz + j] = c;
    }
}

extern "C" void kernel_launch(void* const* d_in, const int* in_sizes, int n_in,
                              void* d_out, int out_size) {
    const float* xin      = (const float*)d_in[0];
    const float* masks    = (const float*)d_in[1];
    const float* h0       = (const float*)d_in[2];
    const float* c0       = (const float*)d_in[3];
    const float* w_ih     = (const float*)d_in[4];
    const float* w_hh     = (const float*)d_in[5];
    const float* b_ih     = (const float*)d_in[6];
    const float* b_hh     = (const float*)d_in[7];
    const float* w_actor  = (const float*)d_in[8];
    const float* b_actor  = (const float*)d_in[9];
    const float* w_critic = (const float*)d_in[10];
    const float* b_critic = (const float*)d_in[11];

    float* out    = (float*)d_out;
    float* actor  = out;
    float* critic = actor + (size_t)Bsz * Tsz * Asz;
    float* hT     = critic + (size_t)Bsz * Tsz;
    float* cT     = hT + (size_t)Bsz * Hsz;

    lstm_fused<<<Bsz / 4, 128>>>(xin, masks, h0, c0, w_ih, w_hh, b_ih, b_hh,
                                 w_actor, b_actor, w_critic, b_critic,
                                 actor, critic, hT, cT);
}

// round 13
// speedup vs baseline: 1.1154x; 1.1154x over previous
#include <cuda_runtime.h>
#include <cstdint>

#define Bsz 2048
#define Tsz 512
#define Asz 32
#define Hsz 16
#define CH 16
#define NCHUNK (Tsz / CH)

typedef unsigned long long u64;
typedef unsigned int u32;

__device__ __forceinline__ void unpack2(u64 v, float& lo, float& hi) {
    asm("mov.b64 {%0, %1}, %2;" : "=f"(lo), "=f"(hi) : "l"(v));
}
__device__ __forceinline__ u64 fma2(u64 a, u64 b, u64 c) {
    u64 d; asm("fma.rn.f32x2 %0, %1, %2, %3;" : "=l"(d) : "l"(a), "l"(b), "l"(c)); return d;
}
__device__ __forceinline__ u64 add2(u64 a, u64 b) {
    u64 d; asm("add.rn.f32x2 %0, %1, %2;" : "=l"(d) : "l"(a), "l"(b)); return d;
}
__device__ __forceinline__ float hsum2(u64 v) {
    float lo, hi; unpack2(v, lo, hi); return lo + hi;
}
__device__ __forceinline__ float tanh_fast(float x) {
    float y; asm("tanh.approx.f32 %0, %1;" : "=f"(y) : "f"(x)); return y;
}
__device__ __forceinline__ float sigmoid_fast(float x) {
    return fmaf(0.5f, tanh_fast(0.5f * x), 0.5f);
}
__device__ __forceinline__ u32 smaddr(const void* p) {
    return (u32)__cvta_generic_to_shared(p);
}
__device__ __forceinline__ void cp16(u32 s, const void* g) {
    asm volatile("cp.async.ca.shared.global [%0], [%1], 16;" :: "r"(s), "l"(g));
}
#define CP_COMMIT() asm volatile("cp.async.commit_group;" ::: "memory")
#define CP_WAIT1()  asm volatile("cp.async.wait_group 1;" ::: "memory")

// ============================================================================
// R11 structure (best: 268.7us), chunk=16, 2-way split gate chains.
// CTA = 128 threads = 4 warps = 2 batch elements.
//   consumer warp (1 elem): recurrence, lo/hi gate split (lane j: i_j,g_j;
//     lane 16+j: f_j,o_j), tanh.approx, 2-way-split accumulator chains.
//   producer warp (1 elem): pregates one chunk AHEAD (cp.async x double
//     buffer) + actor/critic heads one chunk BEHIND (h from 32-deep ring).
// Roles flip with blockIdx parity. One __syncthreads per 16-step chunk.
// ============================================================================
__global__ void __launch_bounds__(128, 4) lstm_fused(
    const float* __restrict__ xin, const float* __restrict__ masks,
    const float* __restrict__ h0, const float* __restrict__ c0,
    const float* __restrict__ w_ih, const float* __restrict__ w_hh,
    const float* __restrict__ b_ih, const float* __restrict__ b_hh,
    const float* __restrict__ w_actor, const float* __restrict__ b_actor,
    const float* __restrict__ w_critic, const float* __restrict__ b_critic,
    float* __restrict__ actor, float* __restrict__ critic,
    float* __restrict__ hT, float* __restrict__ cT)
{
    __shared__ __align__(16) float pgsm[2][2][CH * 64];  // 16KB
    __shared__ __align__(16) float xsm[2][2][CH * 32];   // 8KB
    __shared__ __align__(16) float hbuf[2][32][16];      // 4KB ring: slot t&31 = h_t
    __shared__ __align__(16) float wc_s[16];

    const int tid  = threadIdx.x;
    const int w    = tid >> 5;
    const int lane = tid & 31;
    const int e    = w & 1;                       // element within CTA
    const bool is_prod = ((w >> 1) ^ (blockIdx.x & 1)) != 0;
    const int b    = blockIdx.x * 2 + e;

    if (tid < 16) wc_s[tid] = w_critic[tid];

    if (is_prod) {
        // ---------------- PRODUCER ----------------
        u64 wA[16], wB[16];
        {
            const u64* pA = (const u64*)(w_ih + lane * 32);
            const u64* pB = (const u64*)(w_ih + (32 + lane) * 32);
#pragma unroll
            for (int k = 0; k < 16; k++) { wA[k] = pA[k]; wB[k] = pB[k]; }
        }
        const float bsA = b_ih[lane] + b_hh[lane];
        const float bsB = b_ih[32 + lane] + b_hh[32 + lane];
        u64 wa[8];                                 // actor row = lane
        {
            const u64* pa = (const u64*)(w_actor + lane * 16);
#pragma unroll
            for (int k = 0; k < 8; k++) wa[k] = pa[k];
        }
        const float bact = b_actor[lane];
        const float bcr  = b_critic[0];

        const float* xb = xin + (size_t)b * Tsz * Asz;
        float* actb     = actor + (size_t)b * Tsz * Asz;
        float* crb      = critic + (size_t)b * Tsz;

        auto loadx = [&](int ch) {                 // 16 steps = 512 floats
            const int bf = ch & 1;
            u32 dst = smaddr(&xsm[e][bf][0]);
            const float* src = xb + ch * (CH * 32);
#pragma unroll
            for (int q = 0; q < 4; q++)
                cp16(dst + lane * 16 + q * 512, src + lane * 4 + q * 128);
        };
        auto comp = [&](int ch) {
            const int bf = ch & 1;
#pragma unroll
            for (int s = 0; s < CH; s++) {
                const ulonglong2* xp = (const ulonglong2*)&xsm[e][bf][s * 32];
                u64 a0 = 0, a1 = 0, g0 = 0, g1 = 0;
#pragma unroll
                for (int q = 0; q < 8; q++) {
                    const ulonglong2 v = xp[q];
                    a0 = fma2(wA[2 * q],     v.x, a0);
                    a1 = fma2(wA[2 * q + 1], v.y, a1);
                    g0 = fma2(wB[2 * q],     v.x, g0);
                    g1 = fma2(wB[2 * q + 1], v.y, g1);
                }
                float2 o;
                o.x = hsum2(add2(a0, a1)) + bsA;
                o.y = hsum2(add2(g0, g1)) + bsB;
                *(float2*)&pgsm[e][bf][s * 64 + 2 * lane] = o;
            }
        };
        auto heads = [&](int cc) {                 // chunk cc (h final in ring)
            const int t0 = cc * CH;
#pragma unroll
            for (int s = 0; s < CH; s++) {
                const int t = t0 + s;
                const ulonglong2* hp = (const ulonglong2*)&hbuf[e][t & 31][0];
                u64 a0 = 0, a1 = 0;
#pragma unroll
                for (int q = 0; q < 4; q++) {
                    const ulonglong2 v = hp[q];
                    a0 = fma2(wa[2 * q],     v.x, a0);
                    a1 = fma2(wa[2 * q + 1], v.y, a1);
                }
                actb[t * Asz + lane] = hsum2(add2(a0, a1)) + bact;
            }
            if (lane < 16) {                       // critic: lane = step
                const int t = t0 + lane;
                const u64* hp = (const u64*)&hbuf[e][t & 31][0];
                const u64* wc = (const u64*)wc_s;  // broadcast smem
                u64 a0 = 0, a1 = 0;
#pragma unroll
                for (int k = 0; k < 4; k++) {
                    a0 = fma2(wc[2 * k],     hp[2 * k],     a0);
                    a1 = fma2(wc[2 * k + 1], hp[2 * k + 1], a1);
                }
                crb[t] = hsum2(add2(a0, a1)) + bcr;
            }
        };

        loadx(0); CP_COMMIT();
        loadx(1); CP_COMMIT();
        CP_WAIT1();
        comp(0);
        __syncthreads();                           // pg chunk 0 ready

        for (int cc = 0; cc < NCHUNK; cc++) {
            if (cc + 2 < NCHUNK) loadx(cc + 2);
            CP_COMMIT();
            CP_WAIT1();                            // x_{cc+1} landed
            if (cc + 1 < NCHUNK) comp(cc + 1);
            if (cc >= 1) heads(cc - 1);            // h chunk cc-1 final
            __syncthreads();
        }
        heads(NCHUNK - 1);
    } else {
        // ---------------- CONSUMER (lo/hi gate split, 1 elem) --------------
        const int j = lane & 15;
        const bool hi_half = lane >= 16;

        u64 whP[8], whQ[8];                        // rows lane, 32+lane
        {
            const u64* pP = (const u64*)(w_hh + lane * 16);
            const u64* pQ = (const u64*)(w_hh + (32 + lane) * 16);
#pragma unroll
            for (int k = 0; k < 8; k++) { whP[k] = pP[k]; whQ[k] = pQ[k]; }
        }
        const float* mb = masks + (size_t)b * Tsz;
        float c = c0[b * Hsz + j];
        if (lane < 16) hbuf[e][31][lane] = h0[b * Hsz + lane];  // h_{-1}
        float m_cur = mb[0];
        float h2 = 0.0f;

        __syncthreads();                           // match producer prologue

        for (int cc = 0; cc < NCHUNK; cc++) {
#pragma unroll
            for (int s = 0; s < CH; s++) {
                const int t = cc * CH + s;
                const float m = m_cur;
                m_cur = mb[(t + 1 < Tsz) ? t + 1 : Tsz - 1];
                const float cm = c * m;             // off-chain early

                u64 hv[8];                          // h_{t-1} broadcast
                {
                    const ulonglong2* hp = (const ulonglong2*)&hbuf[e][(t + 31) & 31][0];
#pragma unroll
                    for (int q = 0; q < 4; q++) {
                        const ulonglong2 v = hp[q];
                        hv[2 * q] = v.x; hv[2 * q + 1] = v.y;
                    }
                }
                // 2-way split accumulator chains (depth 4, not 8)
                u64 aP0 = 0, aP1 = 0, aQ0 = 0, aQ1 = 0;
#pragma unroll
                for (int k = 0; k < 4; k++) {
                    aP0 = fma2(whP[2 * k],     hv[2 * k],     aP0);
                    aP1 = fma2(whP[2 * k + 1], hv[2 * k + 1], aP1);
                    aQ0 = fma2(whQ[2 * k],     hv[2 * k],     aQ0);
                    aQ1 = fma2(whQ[2 * k + 1], hv[2 * k + 1], aQ1);
                }
                const float sP = hsum2(add2(aP0, aP1));
                const float sQ = hsum2(add2(aQ0, aQ1));

                const float2 pgv = *(const float2*)&pgsm[e][cc & 1][s * 64 + 2 * lane];

                const float gP = fmaf(m, sP, pgv.x);   // lo: i, hi: f
                const float gQ = fmaf(m, sQ, pgv.y);   // lo: g, hi: o

                const float vP = sigmoid_fast(gP);
                const float tQ = tanh_fast(hi_half ? 0.5f * gQ : gQ);
                const float vQ = hi_half ? fmaf(0.5f, tQ, 0.5f) : tQ;  // o / tanh(g)

                const float p  = vP * vQ;                          // lo: i*g
                const float ig = __shfl_sync(0xffffffffu, p, j);   // hi gets i*g

                c  = fmaf(vP, cm, ig);                             // hi: f*(c*m)+i*g
                h2 = vQ * tanh_fast(c);                            // hi: o*tanh(c)

                if (hi_half) hbuf[e][t & 31][j] = h2;
                __syncwarp();
            }
            __syncthreads();
        }

        if (hi_half) {
            hT[b * Hsz + j] = h2;
            cT[b * Hsz + j] = c;
        }
    }
}

extern "C" void kernel_launch(void* const* d_in, const int* in_sizes, int n_in,
                              void* d_out, int out_size) {
    const float* xin      = (const float*)d_in[0];
    const float* masks    = (const float*)d_in[1];
    const float* h0       = (const float*)d_in[2];
    const float* c0       = (const float*)d_in[3];
    const float* w_ih     = (const float*)d_in[4];
    const float* w_hh     = (const float*)d_in[5];
    const float* b_ih     = (const float*)d_in[6];
    const float* b_hh     = (const float*)d_in[7];
    const float* w_actor  = (const float*)d_in[8];
    const float* b_actor  = (const float*)d_in[9];
    const float* w_critic = (const float*)d_in[10];
    const float* b_critic = (const float*)d_in[11];

    float* out    = (float*)d_out;
    float* actor  = out;
    float* critic = actor + (size_t)Bsz * Tsz * Asz;
    float* hT     = critic + (size_t)Bsz * Tsz;
    float* cT     = hT + (size_t)Bsz * Hsz;

    lstm_fused<<<Bsz / 2, 128>>>(xin, masks, h0, c0, w_ih, w_hh, b_ih, b_hh,
                                 w_actor, b_actor, w_critic, b_critic,
                                 actor, critic, hT, cT);
}

// round 14
// speedup vs baseline: 1.1194x; 1.0037x over previous
#include <cuda_runtime.h>
#include <cstdint>

#define Bsz 2048
#define Tsz 512
#define Asz 32
#define Hsz 16
#define CH 16
#define NCHUNK (Tsz / CH)

typedef unsigned long long u64;
typedef unsigned int u32;

__device__ __forceinline__ void unpack2(u64 v, float& lo, float& hi) {
    asm("mov.b64 {%0, %1}, %2;" : "=f"(lo), "=f"(hi) : "l"(v));
}
__device__ __forceinline__ u64 fma2(u64 a, u64 b, u64 c) {
    u64 d; asm("fma.rn.f32x2 %0, %1, %2, %3;" : "=l"(d) : "l"(a), "l"(b), "l"(c)); return d;
}
__device__ __forceinline__ u64 add2(u64 a, u64 b) {
    u64 d; asm("add.rn.f32x2 %0, %1, %2;" : "=l"(d) : "l"(a), "l"(b)); return d;
}
__device__ __forceinline__ float hsum2(u64 v) {
    float lo, hi; unpack2(v, lo, hi); return lo + hi;
}
__device__ __forceinline__ float tanh_fast(float x) {
    float y; asm("tanh.approx.f32 %0, %1;" : "=f"(y) : "f"(x)); return y;
}
__device__ __forceinline__ float sigmoid_fast(float x) {
    return fmaf(0.5f, tanh_fast(0.5f * x), 0.5f);
}
__device__ __forceinline__ u32 smaddr(const void* p) {
    return (u32)__cvta_generic_to_shared(p);
}
__device__ __forceinline__ void cp16(u32 s, const void* g) {
    asm volatile("cp.async.ca.shared.global [%0], [%1], 16;" :: "r"(s), "l"(g));
}
#define CP_COMMIT() asm volatile("cp.async.commit_group;" ::: "memory")
#define CP_WAIT1()  asm volatile("cp.async.wait_group 1;" ::: "memory")

// ============================================================================
// CTA = 128 threads = 4 warps = 2 batch elements; 5 CTAs/SM (102-reg cap).
//   producer warp (1 elem): x pregates one chunk AHEAD only (w_ih in regs).
//   consumer warp (1 elem): recurrence (lo/hi gate split, tanh.approx,
//     2-way-split chains) + actor/critic heads one chunk BEHIND from its OWN
//     32-deep h ring (no cross-warp dependency; heads fill stall cycles).
// Roles flip with blockIdx parity. One __syncthreads per 16-step chunk
// (guards pgsm only).
// ============================================================================
__global__ void __launch_bounds__(128, 5) lstm_fused(
    const float* __restrict__ xin, const float* __restrict__ masks,
    const float* __restrict__ h0, const float* __restrict__ c0,
    const float* __restrict__ w_ih, const float* __restrict__ w_hh,
    const float* __restrict__ b_ih, const float* __restrict__ b_hh,
    const float* __restrict__ w_actor, const float* __restrict__ b_actor,
    const float* __restrict__ w_critic, const float* __restrict__ b_critic,
    float* __restrict__ actor, float* __restrict__ critic,
    float* __restrict__ hT, float* __restrict__ cT)
{
    __shared__ __align__(16) float pgsm[2][2][CH * 64];  // 16KB
    __shared__ __align__(16) float xsm[2][2][CH * 32];   // 8KB
    __shared__ __align__(16) float hbuf[2][32][16];      // 4KB ring: slot t&31 = h_t
    __shared__ __align__(16) float wact_s[32][18];       // padded actor rows
    __shared__ __align__(16) float wc_s[16];

    const int tid  = threadIdx.x;
    const int w    = tid >> 5;
    const int lane = tid & 31;
    const int e    = w & 1;                       // element within CTA
    const bool is_prod = ((w >> 1) ^ (blockIdx.x & 1)) != 0;
    const int b    = blockIdx.x * 2 + e;

    // stage head weights (padded rows -> u64 pair reads, low-conflict)
    for (int i = tid; i < 512; i += 128)
        wact_s[i >> 4][i & 15] = w_actor[i];
    if (tid < 16) wc_s[tid] = w_critic[tid];

    if (is_prod) {
        // ---------------- PRODUCER: x pregates only ----------------
        u64 wA[16], wB[16];
        {
            const u64* pA = (const u64*)(w_ih + lane * 32);
            const u64* pB = (const u64*)(w_ih + (32 + lane) * 32);
#pragma unroll
            for (int k = 0; k < 16; k++) { wA[k] = pA[k]; wB[k] = pB[k]; }
        }
        const float bsA = b_ih[lane] + b_hh[lane];
        const float bsB = b_ih[32 + lane] + b_hh[32 + lane];

        const float* xb = xin + (size_t)b * Tsz * Asz;

        auto loadx = [&](int ch) {                 // 16 steps = 512 floats
            const int bf = ch & 1;
            u32 dst = smaddr(&xsm[e][bf][0]);
            const float* src = xb + ch * (CH * 32);
#pragma unroll
            for (int q = 0; q < 4; q++)
                cp16(dst + lane * 16 + q * 512, src + lane * 4 + q * 128);
        };
        auto comp = [&](int ch) {
            const int bf = ch & 1;
#pragma unroll
            for (int s = 0; s < CH; s++) {
                const ulonglong2* xp = (const ulonglong2*)&xsm[e][bf][s * 32];
                u64 a0 = 0, a1 = 0, g0 = 0, g1 = 0;
#pragma unroll
                for (int q = 0; q < 8; q++) {
                    const ulonglong2 v = xp[q];
                    a0 = fma2(wA[2 * q],     v.x, a0);
                    a1 = fma2(wA[2 * q + 1], v.y, a1);
                    g0 = fma2(wB[2 * q],     v.x, g0);
                    g1 = fma2(wB[2 * q + 1], v.y, g1);
                }
                float2 o;
                o.x = hsum2(add2(a0, a1)) + bsA;
                o.y = hsum2(add2(g0, g1)) + bsB;
                *(float2*)&pgsm[e][bf][s * 64 + 2 * lane] = o;
            }
        };

        loadx(0); CP_COMMIT();
        loadx(1); CP_COMMIT();
        CP_WAIT1();
        comp(0);
        __syncthreads();                           // pg chunk 0 ready

        for (int cc = 0; cc < NCHUNK; cc++) {
            if (cc + 2 < NCHUNK) loadx(cc + 2);
            CP_COMMIT();
            CP_WAIT1();                            // x_{cc+1} landed
            if (cc + 1 < NCHUNK) comp(cc + 1);
            __syncthreads();
        }
    } else {
        // ---------------- CONSUMER: recurrence + heads ----------------
        const int j = lane & 15;
        const bool hi_half = lane >= 16;

        u64 whP[8], whQ[8];                        // rows lane, 32+lane
        {
            const u64* pP = (const u64*)(w_hh + lane * 16);
            const u64* pQ = (const u64*)(w_hh + (32 + lane) * 16);
#pragma unroll
            for (int k = 0; k < 8; k++) { whP[k] = pP[k]; whQ[k] = pQ[k]; }
        }
        const float bact = b_actor[lane];
        const float bcr  = b_critic[0];

        const float* mb = masks + (size_t)b * Tsz;
        float* actb     = actor + (size_t)b * Tsz * Asz;
        float* crb      = critic + (size_t)b * Tsz;

        float c = c0[b * Hsz + j];
        if (lane < 16) hbuf[e][31][lane] = h0[b * Hsz + lane];  // h_{-1}
        float m_cur = mb[0];
        float h2 = 0.0f;

        // heads for chunk cc (h already final in OWN ring; off critical path)
        auto heads = [&](int cc) {
            u64 wa[8];                             // transient per chunk
            {
                const u64* pw = (const u64*)&wact_s[lane][0];
#pragma unroll
                for (int k = 0; k < 8; k++) wa[k] = pw[k];
            }
            const int t0 = cc * CH;
#pragma unroll
            for (int s = 0; s < CH; s++) {
                const int t = t0 + s;
                const ulonglong2* hp = (const ulonglong2*)&hbuf[e][t & 31][0];
                u64 a0 = 0, a1 = 0;
#pragma unroll
                for (int q = 0; q < 4; q++) {
                    const ulonglong2 v = hp[q];
                    a0 = fma2(wa[2 * q],     v.x, a0);
                    a1 = fma2(wa[2 * q + 1], v.y, a1);
                }
                actb[t * Asz + lane] = hsum2(add2(a0, a1)) + bact;
            }
            if (lane < 16) {                       // critic: lane = step
                const int t = t0 + lane;
                const u64* hp = (const u64*)&hbuf[e][t & 31][0];
                const u64* wc = (const u64*)wc_s;  // broadcast
                u64 a0 = 0, a1 = 0;
#pragma unroll
                for (int k = 0; k < 4; k++) {
                    a0 = fma2(wc[2 * k],     hp[2 * k],     a0);
                    a1 = fma2(wc[2 * k + 1], hp[2 * k + 1], a1);
                }
                crb[t] = hsum2(add2(a0, a1)) + bcr;
            }
        };

        __syncthreads();                           // match producer prologue

        for (int cc = 0; cc < NCHUNK; cc++) {
            if (cc >= 1) heads(cc - 1);
#pragma unroll
            for (int s = 0; s < CH; s++) {
                const int t = cc * CH + s;
                const float m = m_cur;
                m_cur = mb[(t + 1 < Tsz) ? t + 1 : Tsz - 1];
                const float cm = c * m;             // off-chain early

                u64 hv[8];                          // h_{t-1} broadcast
                {
                    const ulonglong2* hp = (const ulonglong2*)&hbuf[e][(t + 31) & 31][0];
#pragma unroll
                    for (int q = 0; q < 4; q++) {
                        const ulonglong2 v = hp[q];
                        hv[2 * q] = v.x; hv[2 * q + 1] = v.y;
                    }
                }
                u64 aP0 = 0, aP1 = 0, aQ0 = 0, aQ1 = 0;
#pragma unroll
                for (int k = 0; k < 4; k++) {
                    aP0 = fma2(whP[2 * k],     hv[2 * k],     aP0);
                    aP1 = fma2(whP[2 * k + 1], hv[2 * k + 1], aP1);
                    aQ0 = fma2(whQ[2 * k],     hv[2 * k],     aQ0);
                    aQ1 = fma2(whQ[2 * k + 1], hv[2 * k + 1], aQ1);
                }
                const float sP = hsum2(add2(aP0, aP1));
                const float sQ = hsum2(add2(aQ0, aQ1));

                const float2 pgv = *(const float2*)&pgsm[e][cc & 1][s * 64 + 2 * lane];

                const float gP = fmaf(m, sP, pgv.x);   // lo: i, hi: f
                const float gQ = fmaf(m, sQ, pgv.y);   // lo: g, hi: o

                const float vP = sigmoid_fast(gP);
                const float tQ = tanh_fast(hi_half ? 0.5f * gQ : gQ);
                const float vQ = hi_half ? fmaf(0.5f, tQ, 0.5f) : tQ;  // o / tanh(g)

                const float p  = vP * vQ;                          // lo: i*g
                const float ig = __shfl_sync(0xffffffffu, p, j);   // hi gets i*g

                c  = fmaf(vP, cm, ig);                             // hi: f*(c*m)+i*g
                h2 = vQ * tanh_fast(c);                            // hi: o*tanh(c)

                if (hi_half) hbuf[e][t & 31][j] = h2;
                __syncwarp();
            }
            __syncthreads();
        }
        heads(NCHUNK - 1);                         // own-ring data; no barrier

        if (hi_half) {
            hT[b * Hsz + j] = h2;
            cT[b * Hsz + j] = c;
        }
    }
}

extern "C" void kernel_launch(void* const* d_in, const int* in_sizes, int n_in,
                              void* d_out, int out_size) {
    const float* xin      = (const float*)d_in[0];
    const float* masks    = (const float*)d_in[1];
    const float* h0       = (const float*)d_in[2];
    const float* c0       = (const float*)d_in[3];
    const float* w_ih     = (const float*)d_in[4];
    const float* w_hh     = (const float*)d_in[5];
    const float* b_ih     = (const float*)d_in[6];
    const float* b_hh     = (const float*)d_in[7];
    const float* w_actor  = (const float*)d_in[8];
    const float* b_actor  = (const float*)d_in[9];
    const float* w_critic = (const float*)d_in[10];
    const float* b_critic = (const float*)d_in[11];

    float* out    = (float*)d_out;
    float* actor  = out;
    float* critic = actor + (size_t)Bsz * Tsz * Asz;
    float* hT     = critic + (size_t)Bsz * Tsz;
    float* cT     = hT + (size_t)Bsz * Hsz;

    lstm_fused<<<Bsz / 2, 128>>>(xin, masks, h0, c0, w_ih, w_hh, b_ih, b_hh,
                                 w_actor, b_actor, w_critic, b_critic,
                                 actor, critic, hT, cT);
}

// round 15
// speedup vs baseline: 1.1748x; 1.0494x over previous
#include <cuda_runtime.h>
#include <cstdint>

#define Bsz 2048
#define Tsz 512
#define Asz 32
#define Hsz 16
#define CH 16
#define NCHUNK (Tsz / CH)

typedef unsigned long long u64;
typedef unsigned int u32;

__device__ __forceinline__ void unpack2(u64 v, float& lo, float& hi) {
    asm("mov.b64 {%0, %1}, %2;" : "=f"(lo), "=f"(hi) : "l"(v));
}
__device__ __forceinline__ u64 fma2(u64 a, u64 b, u64 c) {
    u64 d; asm("fma.rn.f32x2 %0, %1, %2, %3;" : "=l"(d) : "l"(a), "l"(b), "l"(c)); return d;
}
__device__ __forceinline__ u64 add2(u64 a, u64 b) {
    u64 d; asm("add.rn.f32x2 %0, %1, %2;" : "=l"(d) : "l"(a), "l"(b)); return d;
}
__device__ __forceinline__ float hsum2(u64 v) {
    float lo, hi; unpack2(v, lo, hi); return lo + hi;
}
__device__ __forceinline__ float tanh_fast(float x) {
    float y; asm("tanh.approx.f32 %0, %1;" : "=f"(y) : "f"(x)); return y;
}
__device__ __forceinline__ float sigmoid_fast(float x) {
    return fmaf(0.5f, tanh_fast(0.5f * x), 0.5f);
}
__device__ __forceinline__ u32 smaddr(const void* p) {
    return (u32)__cvta_generic_to_shared(p);
}
__device__ __forceinline__ void cp16(u32 s, const void* g) {
    asm volatile("cp.async.ca.shared.global [%0], [%1], 16;" :: "r"(s), "l"(g));
}
#define CP_COMMIT() asm volatile("cp.async.commit_group;" ::: "memory")
#define CP_WAIT1()  asm volatile("cp.async.wait_group 1;" ::: "memory")

// ============================================================================
// CTA = 128 threads = 4 warps = 2 batch elements; 5 CTAs/SM.
//   producer warp (1 elem): x pregates one chunk AHEAD only.
//   consumer warp (1 elem): recurrence (lo/hi gate split, tanh.approx) with
//     the ACTOR HEAD FUSED INTO THE STEP, reusing the hv registers already
//     loaded for the gates (kills the head pass's 4xLDS.128/step). Critic
//     stays one chunk BEHIND (8 wavefronts/chunk from the h ring).
//     Masks batched as float4 (4 LDG / 16 steps).
// Roles flip with blockIdx parity. One __syncthreads per 16-step chunk.
// ============================================================================
__global__ void __launch_bounds__(128, 5) lstm_fused(
    const float* __restrict__ xin, const float* __restrict__ masks,
    const float* __restrict__ h0, const float* __restrict__ c0,
    const float* __restrict__ w_ih, const float* __restrict__ w_hh,
    const float* __restrict__ b_ih, const float* __restrict__ b_hh,
    const float* __restrict__ w_actor, const float* __restrict__ b_actor,
    const float* __restrict__ w_critic, const float* __restrict__ b_critic,
    float* __restrict__ actor, float* __restrict__ critic,
    float* __restrict__ hT, float* __restrict__ cT)
{
    __shared__ __align__(16) float pgsm[2][2][CH * 64];  // 16KB
    __shared__ __align__(16) float xsm[2][2][CH * 32];   // 8KB
    __shared__ __align__(16) float hbuf[2][32][16];      // ring: slot t&31 = h_t
    __shared__ __align__(16) float wc_s[16];

    const int tid  = threadIdx.x;
    const int w    = tid >> 5;
    const int lane = tid & 31;
    const int e    = w & 1;
    const bool is_prod = ((w >> 1) ^ (blockIdx.x & 1)) != 0;
    const int b    = blockIdx.x * 2 + e;

    if (tid < 16) wc_s[tid] = w_critic[tid];

    if (is_prod) {
        // ---------------- PRODUCER: x pregates only ----------------
        u64 wA[16], wB[16];
        {
            const u64* pA = (const u64*)(w_ih + lane * 32);
            const u64* pB = (const u64*)(w_ih + (32 + lane) * 32);
#pragma unroll
            for (int k = 0; k < 16; k++) { wA[k] = pA[k]; wB[k] = pB[k]; }
        }
        const float bsA = b_ih[lane] + b_hh[lane];
        const float bsB = b_ih[32 + lane] + b_hh[32 + lane];

        const float* xb = xin + (size_t)b * Tsz * Asz;

        auto loadx = [&](int ch) {
            const int bf = ch & 1;
            u32 dst = smaddr(&xsm[e][bf][0]);
            const float* src = xb + ch * (CH * 32);
#pragma unroll
            for (int q = 0; q < 4; q++)
                cp16(dst + lane * 16 + q * 512, src + lane * 4 + q * 128);
        };
        auto comp = [&](int ch) {
            const int bf = ch & 1;
#pragma unroll
            for (int s = 0; s < CH; s++) {
                const ulonglong2* xp = (const ulonglong2*)&xsm[e][bf][s * 32];
                u64 a0 = 0, a1 = 0, g0 = 0, g1 = 0;
#pragma unroll
                for (int q = 0; q < 8; q++) {
                    const ulonglong2 v = xp[q];
                    a0 = fma2(wA[2 * q],     v.x, a0);
                    a1 = fma2(wA[2 * q + 1], v.y, a1);
                    g0 = fma2(wB[2 * q],     v.x, g0);
                    g1 = fma2(wB[2 * q + 1], v.y, g1);
                }
                float2 o;
                o.x = hsum2(add2(a0, a1)) + bsA;
                o.y = hsum2(add2(g0, g1)) + bsB;
                *(float2*)&pgsm[e][bf][s * 64 + 2 * lane] = o;
            }
        };

        loadx(0); CP_COMMIT();
        loadx(1); CP_COMMIT();
        CP_WAIT1();
        comp(0);
        __syncthreads();

        for (int cc = 0; cc < NCHUNK; cc++) {
            if (cc + 2 < NCHUNK) loadx(cc + 2);
            CP_COMMIT();
            CP_WAIT1();
            if (cc + 1 < NCHUNK) comp(cc + 1);
            __syncthreads();
        }
    } else {
        // ---------------- CONSUMER: recurrence + fused actor ----------------
        const int j = lane & 15;
        const bool hi_half = lane >= 16;

        u64 whP[8], whQ[8];                        // rows lane, 32+lane
        {
            const u64* pP = (const u64*)(w_hh + lane * 16);
            const u64* pQ = (const u64*)(w_hh + (32 + lane) * 16);
#pragma unroll
            for (int k = 0; k < 8; k++) { whP[k] = pP[k]; whQ[k] = pQ[k]; }
        }
        u64 wa[8];                                 // actor row = lane
        {
            const u64* pa = (const u64*)(w_actor + lane * 16);
#pragma unroll
            for (int k = 0; k < 8; k++) wa[k] = pa[k];
        }
        const float bact = b_actor[lane];
        const float bcr  = b_critic[0];

        const float* mb = masks + (size_t)b * Tsz;
        float* actb     = actor + (size_t)b * Tsz * Asz;
        float* crb      = critic + (size_t)b * Tsz;

        float c = c0[b * Hsz + j];
        if (lane < 16) hbuf[e][31][lane] = h0[b * Hsz + lane];  // h_{-1}
        float h2 = 0.0f;

        // critic for chunk cc (h final in OWN ring)
        auto critic_pass = [&](int cc) {
            if (lane < 16) {                       // lane = step within chunk
                const int t = cc * CH + lane;
                const u64* hp = (const u64*)&hbuf[e][t & 31][0];
                const u64* wc = (const u64*)wc_s;
                u64 a0 = 0, a1 = 0;
#pragma unroll
                for (int k = 0; k < 4; k++) {
                    a0 = fma2(wc[2 * k],     hp[2 * k],     a0);
                    a1 = fma2(wc[2 * k + 1], hp[2 * k + 1], a1);
                }
                crb[t] = hsum2(add2(a0, a1)) + bcr;
            }
        };

        __syncthreads();                           // match producer prologue

        float4 mv4 = make_float4(0.f, 0.f, 0.f, 0.f);

        for (int cc = 0; cc < NCHUNK; cc++) {
            if (cc >= 1) critic_pass(cc - 1);
#pragma unroll
            for (int s = 0; s < CH; s++) {
                const int t = cc * CH + s;
                if ((s & 3) == 0) mv4 = *(const float4*)&mb[t];
                const float m = (s & 3) == 0 ? mv4.x
                              : (s & 3) == 1 ? mv4.y
                              : (s & 3) == 2 ? mv4.z : mv4.w;
                const float cm = c * m;

                u64 hv[8];                          // h_{t-1} broadcast
                {
                    const ulonglong2* hp = (const ulonglong2*)&hbuf[e][(t + 31) & 31][0];
#pragma unroll
                    for (int q = 0; q < 4; q++) {
                        const ulonglong2 v = hp[q];
                        hv[2 * q] = v.x; hv[2 * q + 1] = v.y;
                    }
                }
                // ---- fused actor head for step t-1 (reuses hv; no extra LDS)
                {
                    u64 A0 = 0, A1 = 0;
#pragma unroll
                    for (int k = 0; k < 4; k++) {
                        A0 = fma2(wa[2 * k],     hv[2 * k],     A0);
                        A1 = fma2(wa[2 * k + 1], hv[2 * k + 1], A1);
                    }
                    const float av = hsum2(add2(A0, A1)) + bact;
                    if (t > 0) actb[(t - 1) * Asz + lane] = av;
                }
                // ---- gates
                u64 aP0 = 0, aP1 = 0, aQ0 = 0, aQ1 = 0;
#pragma unroll
                for (int k = 0; k < 4; k++) {
                    aP0 = fma2(whP[2 * k],     hv[2 * k],     aP0);
                    aP1 = fma2(whP[2 * k + 1], hv[2 * k + 1], aP1);
                    aQ0 = fma2(whQ[2 * k],     hv[2 * k],     aQ0);
                    aQ1 = fma2(whQ[2 * k + 1], hv[2 * k + 1], aQ1);
                }
                const float sP = hsum2(add2(aP0, aP1));
                const float sQ = hsum2(add2(aQ0, aQ1));

                const float2 pgv = *(const float2*)&pgsm[e][cc & 1][s * 64 + 2 * lane];

                const float gP = fmaf(m, sP, pgv.x);   // lo: i, hi: f
                const float gQ = fmaf(m, sQ, pgv.y);   // lo: g, hi: o

                const float vP = sigmoid_fast(gP);
                const float tQ = tanh_fast(hi_half ? 0.5f * gQ : gQ);
                const float vQ = hi_half ? fmaf(0.5f, tQ, 0.5f) : tQ;

                const float p  = vP * vQ;                          // lo: i*g
                const float ig = __shfl_sync(0xffffffffu, p, j);   // hi gets i*g

                c  = fmaf(vP, cm, ig);                             // hi lanes
                h2 = vQ * tanh_fast(c);                            // hi lanes

                if (hi_half) hbuf[e][t & 31][j] = h2;
                __syncwarp();
            }
            __syncthreads();
        }
        critic_pass(NCHUNK - 1);                   // own-ring data

        // tail: actor for t = Tsz-1 (h_511 in ring slot 511&31 = 31)
        {
            u64 hv[8];
            const ulonglong2* hp = (const ulonglong2*)&hbuf[e][(Tsz - 1) & 31][0];
#pragma unroll
            for (int q = 0; q < 4; q++) {
                const ulonglong2 v = hp[q];
                hv[2 * q] = v.x; hv[2 * q + 1] = v.y;
            }
            u64 A0 = 0, A1 = 0;
#pragma unroll
            for (int k = 0; k < 4; k++) {
                A0 = fma2(wa[2 * k],     hv[2 * k],     A0);
                A1 = fma2(wa[2 * k + 1], hv[2 * k + 1], A1);
            }
            actb[(Tsz - 1) * Asz + lane] = hsum2(add2(A0, A1)) + bact;
        }

        if (hi_half) {
            hT[b * Hsz + j] = h2;
            cT[b * Hsz + j] = c;
        }
    }
}

extern "C" void kernel_launch(void* const* d_in, const int* in_sizes, int n_in,
                              void* d_out, int out_size) {
    const float* xin      = (const float*)d_in[0];
    const float* masks    = (const float*)d_in[1];
    const float* h0       = (const float*)d_in[2];
    const float* c0       = (const float*)d_in[3];
    const float* w_ih     = (const float*)d_in[4];
    const float* w_hh     = (const float*)d_in[5];
    const float* b_ih     = (const float*)d_in[6];
    const float* b_hh     = (const float*)d_in[7];
    const float* w_actor  = (const float*)d_in[8];
    const float* b_actor  = (const float*)d_in[9];
    const float* w_critic = (const float*)d_in[10];
    const float* b_critic = (const float*)d_in[11];

    float* out    = (float*)d_out;
    float* actor  = out;
    float* critic = actor + (size_t)Bsz * Tsz * Asz;
    float* hT     = critic + (size_t)Bsz * Tsz;
    float* cT     = hT + (size_t)Bsz * Hsz;

    lstm_fused<<<Bsz / 2, 128>>>(xin, masks, h0, c0, w_ih, w_hh, b_ih, b_hh,
                                 w_actor, b_actor, w_critic, b_critic,
                                 actor, critic, hT, cT);
}